// round 10
// baseline (speedup 1.0000x reference)
#include <cuda_runtime.h>
#include <cuda_fp16.h>
#include <cstdint>

// ============================================================================
// CLinear: out[M,N] = x[M,K] @ dequant(W)[N,K]^T + bias
// M=8192, N=4096, K=4096. Base-compute_103-safe: mma.sync fp16 + cp.async.
// R10: fragment double-buffering across ks (LDSM for ks+1 issued before MMAs
//      of ks); cp.async addresses computed inline to pay the register bill.
//      GEMM shape = validated R7/R8/R9 config (128x128, warp 64x32, 3 stages,
//      2 CTAs/SM). Prep = validated R9 wide-vector version.
// ============================================================================

#define K_DIM 4096
#define N_DIM 4096
#define NUM_GROUPS 64
#define M_MAX 8192

#define BM 128
#define BN 128
#define BK 64
#define KT_COUNT (K_DIM / BK)      // 64
#define STAGES 3
#define A_BYTES (BM * BK * 2)      // 16384
#define B_BYTES (BN * BK * 2)      // 16384
#define STAGE_BYTES (A_BYTES + B_BYTES)          // 32768
#define SMEM_TOTAL (STAGES * STAGE_BYTES)        // 98304 -> 2 CTAs/SM
#define NT 256

// fp16 scratch (device globals: the only legal scratch)
__device__ __half g_xh[(size_t)M_MAX * K_DIM];   // 64 MB
__device__ __half g_wh[(size_t)N_DIM * K_DIM];   // 32 MB

// ---------------------------------------------------------------------------
__device__ __forceinline__ uint32_t smem_u32(const void* p) {
    uint32_t a;
    asm("{ .reg .u64 t; cvta.to.shared.u64 t, %1; cvt.u32.u64 %0, t; }"
        : "=r"(a) : "l"(p));
    return a;
}
// 16B-atom xor swizzle within a 128B row: atom col c (0..7), row r
__device__ __forceinline__ uint32_t swz(uint32_t row, uint32_t c) {
    return row * 128u + ((c ^ (row & 7u)) << 4);
}

#define CP_ASYNC16(dst, src) \
    asm volatile("cp.async.cg.shared.global [%0], [%1], 16;" :: "r"(dst), "l"(src))
#define CP_COMMIT() asm volatile("cp.async.commit_group;")
#define CP_WAIT1()  asm volatile("cp.async.wait_group 1;")

#define LDM_X4(r0, r1, r2, r3, a) \
    asm volatile("ldmatrix.sync.aligned.m8n8.x4.shared.b16 {%0,%1,%2,%3}, [%4];" \
                 : "=r"(r0), "=r"(r1), "=r"(r2), "=r"(r3) : "r"(a))

#define MMA16816(d, a, b)                                                      \
    asm volatile(                                                              \
        "mma.sync.aligned.m16n8k16.row.col.f32.f16.f16.f32 "                   \
        "{%0,%1,%2,%3}, {%4,%5,%6,%7}, {%8,%9}, {%0,%1,%2,%3};"                \
        : "+f"((d)[0]), "+f"((d)[1]), "+f"((d)[2]), "+f"((d)[3])               \
        : "r"((a)[0]), "r"((a)[1]), "r"((a)[2]), "r"((a)[3]),                  \
          "r"((b)[0]), "r"((b)[1]))

// ---------------------------------------------------------------------------
// fused prep: blocks [0, xblocks) convert x -> fp16 (8 floats/thread);
// the rest dequant W (one int4 = 4 packed bytes = 8 weights per thread).
// ---------------------------------------------------------------------------
__global__ __launch_bounds__(512)
void prep_kernel(const float* __restrict__ x,
                 const int* __restrict__ packed,
                 const float* __restrict__ mn,
                 const float* __restrict__ scale,
                 int xblocks) {
    if ((int)blockIdx.x < xblocks) {
        size_t t = (size_t)blockIdx.x * 512 + threadIdx.x;
        const float4* xv = reinterpret_cast<const float4*>(x);
        float4 v0 = __ldcs(xv + t * 2);
        float4 v1 = __ldcs(xv + t * 2 + 1);
        __half2 h0 = __floats2half2_rn(v0.x, v0.y);
        __half2 h1 = __floats2half2_rn(v0.z, v0.w);
        __half2 h2 = __floats2half2_rn(v1.x, v1.y);
        __half2 h3 = __floats2half2_rn(v1.z, v1.w);
        uint4 o;
        o.x = *reinterpret_cast<uint32_t*>(&h0);
        o.y = *reinterpret_cast<uint32_t*>(&h1);
        o.z = *reinterpret_cast<uint32_t*>(&h2);
        o.w = *reinterpret_cast<uint32_t*>(&h3);
        __stcs(reinterpret_cast<uint4*>(g_xh + t * 8), o);
    } else {
        uint32_t t = (blockIdx.x - xblocks) * 512 + threadIdx.x;
        uint32_t n   = t >> 9;             // 512 int4 per n row
        uint32_t rem = t & 511;
        uint32_t g   = rem >> 3;           // group
        uint32_t j4  = rem & 7;            // int4 within group (j = j4*4)
        int4 p = __ldcs(reinterpret_cast<const int4*>(packed) + t);
        float rcp = 1.0f / __ldg(scale + n * NUM_GROUPS + g);
        float mv  = __ldg(mn + n * NUM_GROUPS + g);
        int pv[4] = {p.x, p.y, p.z, p.w};
        __half hi[4], lo[4];
#pragma unroll
        for (int b = 0; b < 4; b++) {
            hi[b] = __float2half_rn((float)((pv[b] >> 4) & 0xF) * rcp + mv);
            lo[b] = __float2half_rn((float)(pv[b] & 0xF) * rcp + mv);
        }
        size_t base = (size_t)n * K_DIM + g * 64 + j4 * 4;
        __stcs(reinterpret_cast<uint2*>(g_wh + base),
               *reinterpret_cast<uint2*>(hi));
        __stcs(reinterpret_cast<uint2*>(g_wh + base + 32),
               *reinterpret_cast<uint2*>(lo));
    }
}

// ---------------------------------------------------------------------------
// GEMM: 256 threads (8 warps), warp tile 64x32, 3-stage cp.async pipeline,
// 2 CTAs/SM, fragment double-buffering across ks.
// ---------------------------------------------------------------------------
__global__ __launch_bounds__(NT, 2)
void gemm_kernel(const float* __restrict__ bias, float* __restrict__ out) {
    extern __shared__ char smem[];
    const uint32_t sb = smem_u32(smem);
    const int tid = threadIdx.x;
    const int lane = tid & 31;
    const int wid = tid >> 5;
    const int warp_m = wid & 1;        // 2 warps along M
    const int warp_n = wid >> 1;       // 4 warps along N
    const int m_base = warp_m * 64;
    const int n_base = warp_n * 32;
    const int m0 = blockIdx.y * BM;
    const int n0 = blockIdx.x * BN;

    const char* gxb = (const char*)g_xh;
    const char* gwb = (const char*)g_wh;

    float acc[4][4][4];
#pragma unroll
    for (int i = 0; i < 4; i++)
#pragma unroll
        for (int j = 0; j < 4; j++)
#pragma unroll
            for (int q = 0; q < 4; q++) acc[i][j][q] = 0.0f;

    // ldmatrix per-thread row components
    const uint32_t a_row = m_base + (lane & 15);       // + i*16
    const uint32_t a_kh  = (lane >> 4) & 1;
    const uint32_t b_row = n_base + (((lane >> 4) & 1) << 3) + (lane & 7); // + jj*16
    const uint32_t b_kh  = (lane >> 3) & 1;

    // inline cp.async of one kt-slab into stage at soff
#define LOAD_STAGE(soff, koff)                                                 \
    do {                                                                       \
        _Pragma("unroll")                                                      \
        for (int i = 0; i < 4; i++) {                                          \
            uint32_t idx = tid + i * NT;                                       \
            uint32_t r = idx >> 3, c = idx & 7;                                \
            uint32_t sw = swz(r, c);                                           \
            CP_ASYNC16((soff) + sw,                                            \
                       gxb + ((uint32_t)(m0 + r) * K_DIM + c * 8) * 2 + (koff)); \
            CP_ASYNC16((soff) + A_BYTES + sw,                                  \
                       gwb + ((uint32_t)(n0 + r) * K_DIM + c * 8) * 2 + (koff)); \
        }                                                                      \
    } while (0)

    // fragment load for one ks into buffer b
#define LOAD_FRAGS(ks, b, As, Bs)                                              \
    do {                                                                       \
        _Pragma("unroll")                                                      \
        for (int i = 0; i < 4; i++) {                                          \
            uint32_t addr = (As) + swz(a_row + i * 16, (ks) * 2 + a_kh);       \
            LDM_X4(afr[b][i][0], afr[b][i][1], afr[b][i][2], afr[b][i][3], addr); \
        }                                                                      \
        _Pragma("unroll")                                                      \
        for (int jj = 0; jj < 2; jj++) {                                       \
            uint32_t addr = (Bs) + swz(b_row + jj * 16, (ks) * 2 + b_kh);      \
            uint32_t r0, r1, r2, r3;                                           \
            LDM_X4(r0, r1, r2, r3, addr);                                      \
            bfr[b][jj * 2][0] = r0;     bfr[b][jj * 2][1] = r1;                \
            bfr[b][jj * 2 + 1][0] = r2; bfr[b][jj * 2 + 1][1] = r3;            \
        }                                                                      \
    } while (0)

    // ---- prologue: stages 0..1 ----
#pragma unroll
    for (int s = 0; s < STAGES - 1; s++)
        { LOAD_STAGE(sb + s * STAGE_BYTES, (uint32_t)s * BK * 2); CP_COMMIT(); }

    uint32_t afr[2][4][4];
    uint32_t bfr[2][4][2];

    int stage = 0;          // stage holding kt
#pragma unroll 1
    for (int kt = 0; kt < KT_COUNT; kt++) {
        CP_WAIT1();
        __syncthreads();

        // prefetch kt+2 into the stage freed at kt-1
        {
            int pf = kt + STAGES - 1;
            if (pf < KT_COUNT) {
                int sp = stage + 2;
                if (sp >= STAGES) sp -= STAGES;
                LOAD_STAGE(sb + sp * STAGE_BYTES, (uint32_t)pf * BK * 2);
            }
            CP_COMMIT();   // empty group when done keeps wait invariant
        }

        uint32_t As = sb + stage * STAGE_BYTES;
        uint32_t Bs = As + A_BYTES;
        stage++; if (stage >= STAGES) stage = 0;

        LOAD_FRAGS(0, 0, As, Bs);
#pragma unroll
        for (int ks = 0; ks < 4; ks++) {
            const int cur = ks & 1;
            const int nxt = cur ^ 1;
            if (ks < 3) LOAD_FRAGS(ks + 1, nxt, As, Bs);
#pragma unroll
            for (int i = 0; i < 4; i++)
#pragma unroll
                for (int j = 0; j < 4; j++)
                    MMA16816(acc[i][j], afr[cur][i], bfr[cur][j]);
        }
    }

    // ---- epilogue: bias + streaming stores ----
    const int tq = lane >> 2;          // row within 16
    const int tr = lane & 3;           // col pair
#pragma unroll
    for (int i = 0; i < 4; i++) {
        size_t mrow0 = (size_t)m0 + m_base + i * 16 + tq;
#pragma unroll
        for (int j = 0; j < 4; j++) {
            int ncol = n0 + n_base + j * 8 + tr * 2;
            float2 bv = __ldg(reinterpret_cast<const float2*>(bias + ncol));
            float2 v0 = {acc[i][j][0] + bv.x, acc[i][j][1] + bv.y};
            float2 v1 = {acc[i][j][2] + bv.x, acc[i][j][3] + bv.y};
            __stcs(reinterpret_cast<float2*>(out + mrow0 * N_DIM + ncol), v0);
            __stcs(reinterpret_cast<float2*>(out + (mrow0 + 8) * N_DIM + ncol), v1);
        }
    }
#undef LOAD_STAGE
#undef LOAD_FRAGS
}

// ---------------------------------------------------------------------------
extern "C" void kernel_launch(void* const* d_in, const int* in_sizes, int n_in,
                              void* d_out, int out_size) {
    const float* x      = (const float*)d_in[0];
    const int*   packed = (const int*)d_in[1];
    const float* mn     = (const float*)d_in[2];
    const float* scale  = (const float*)d_in[3];
    const float* bias   = (const float*)d_in[4];
    float* out = (float*)d_out;

    const int M = in_sizes[0] / K_DIM;                 // 8192

    cudaFuncSetAttribute(gemm_kernel,
                         cudaFuncAttributeMaxDynamicSharedMemorySize, SMEM_TOTAL);

    const int xblocks = (int)(((size_t)M * K_DIM / 8) / 512);            // 8192
    const int wblocks = (N_DIM * NUM_GROUPS * 8) / 512;                  // 4096
    prep_kernel<<<xblocks + wblocks, 512>>>(x, packed, mn, scale, xblocks);

    dim3 grid(N_DIM / BN, M / BM);                     // (32, 64)
    gemm_kernel<<<grid, NT, SMEM_TOTAL>>>(bias, out);
}

// round 11
// speedup vs baseline: 1.0946x; 1.0946x over previous
#include <cuda_runtime.h>
#include <cuda_fp16.h>
#include <cstdint>

// ============================================================================
// CLinear: out[M,N] = x[M,K] @ dequant(W)[N,K]^T + bias
// M=8192, N=4096, K=4096. Base-compute_103-safe: mma.sync fp16 + cp.async.
// R11: R9 kernel (best: 616.8us) with one change — the per-kt cp.async
//      prefetch block is issued AFTER the ks=0 fragment-load+MMA burst, so
//      tensor work starts immediately at the top of each kt iteration.
// ============================================================================

#define K_DIM 4096
#define N_DIM 4096
#define NUM_GROUPS 64
#define M_MAX 8192

#define BM 128
#define BN 128
#define BK 64
#define KT_COUNT (K_DIM / BK)      // 64
#define STAGES 3
#define A_BYTES (BM * BK * 2)      // 16384
#define B_BYTES (BN * BK * 2)      // 16384
#define STAGE_BYTES (A_BYTES + B_BYTES)          // 32768
#define SMEM_TOTAL (STAGES * STAGE_BYTES)        // 98304 -> 2 CTAs/SM
#define NT 256

// fp16 scratch (device globals: the only legal scratch)
__device__ __half g_xh[(size_t)M_MAX * K_DIM];   // 64 MB
__device__ __half g_wh[(size_t)N_DIM * K_DIM];   // 32 MB

// ---------------------------------------------------------------------------
__device__ __forceinline__ uint32_t smem_u32(const void* p) {
    uint32_t a;
    asm("{ .reg .u64 t; cvta.to.shared.u64 t, %1; cvt.u32.u64 %0, t; }"
        : "=r"(a) : "l"(p));
    return a;
}
// 16B-atom xor swizzle within a 128B row: atom col c (0..7), row r
__device__ __forceinline__ uint32_t swz(uint32_t row, uint32_t c) {
    return row * 128u + ((c ^ (row & 7u)) << 4);
}

#define CP_ASYNC16(dst, src) \
    asm volatile("cp.async.cg.shared.global [%0], [%1], 16;" :: "r"(dst), "l"(src))
#define CP_COMMIT() asm volatile("cp.async.commit_group;")
#define CP_WAIT1()  asm volatile("cp.async.wait_group 1;")

#define LDM_X4(r0, r1, r2, r3, a) \
    asm volatile("ldmatrix.sync.aligned.m8n8.x4.shared.b16 {%0,%1,%2,%3}, [%4];" \
                 : "=r"(r0), "=r"(r1), "=r"(r2), "=r"(r3) : "r"(a))

#define MMA16816(d, a, b)                                                      \
    asm volatile(                                                              \
        "mma.sync.aligned.m16n8k16.row.col.f32.f16.f16.f32 "                   \
        "{%0,%1,%2,%3}, {%4,%5,%6,%7}, {%8,%9}, {%0,%1,%2,%3};"                \
        : "+f"((d)[0]), "+f"((d)[1]), "+f"((d)[2]), "+f"((d)[3])               \
        : "r"((a)[0]), "r"((a)[1]), "r"((a)[2]), "r"((a)[3]),                  \
          "r"((b)[0]), "r"((b)[1]))

// ---------------------------------------------------------------------------
// fused prep: blocks [0, xblocks) convert x -> fp16 (8 floats/thread);
// the rest dequant W (one int4 = 4 packed bytes = 8 weights per thread).
// ---------------------------------------------------------------------------
__global__ __launch_bounds__(512)
void prep_kernel(const float* __restrict__ x,
                 const int* __restrict__ packed,
                 const float* __restrict__ mn,
                 const float* __restrict__ scale,
                 int xblocks) {
    if ((int)blockIdx.x < xblocks) {
        size_t t = (size_t)blockIdx.x * 512 + threadIdx.x;
        const float4* xv = reinterpret_cast<const float4*>(x);
        float4 v0 = __ldcs(xv + t * 2);
        float4 v1 = __ldcs(xv + t * 2 + 1);
        __half2 h0 = __floats2half2_rn(v0.x, v0.y);
        __half2 h1 = __floats2half2_rn(v0.z, v0.w);
        __half2 h2 = __floats2half2_rn(v1.x, v1.y);
        __half2 h3 = __floats2half2_rn(v1.z, v1.w);
        uint4 o;
        o.x = *reinterpret_cast<uint32_t*>(&h0);
        o.y = *reinterpret_cast<uint32_t*>(&h1);
        o.z = *reinterpret_cast<uint32_t*>(&h2);
        o.w = *reinterpret_cast<uint32_t*>(&h3);
        __stcs(reinterpret_cast<uint4*>(g_xh + t * 8), o);
    } else {
        uint32_t t = (blockIdx.x - xblocks) * 512 + threadIdx.x;
        uint32_t n   = t >> 9;             // 512 int4 per n row
        uint32_t rem = t & 511;
        uint32_t g   = rem >> 3;           // group
        uint32_t j4  = rem & 7;            // int4 within group (j = j4*4)
        int4 p = __ldcs(reinterpret_cast<const int4*>(packed) + t);
        float rcp = 1.0f / __ldg(scale + n * NUM_GROUPS + g);
        float mv  = __ldg(mn + n * NUM_GROUPS + g);
        int pv[4] = {p.x, p.y, p.z, p.w};
        __half hi[4], lo[4];
#pragma unroll
        for (int b = 0; b < 4; b++) {
            hi[b] = __float2half_rn((float)((pv[b] >> 4) & 0xF) * rcp + mv);
            lo[b] = __float2half_rn((float)(pv[b] & 0xF) * rcp + mv);
        }
        size_t base = (size_t)n * K_DIM + g * 64 + j4 * 4;
        __stcs(reinterpret_cast<uint2*>(g_wh + base),
               *reinterpret_cast<uint2*>(hi));
        __stcs(reinterpret_cast<uint2*>(g_wh + base + 32),
               *reinterpret_cast<uint2*>(lo));
    }
}

// ---------------------------------------------------------------------------
// GEMM: 256 threads (8 warps), warp tile 64x32, 3-stage pipeline, occ 2
// ---------------------------------------------------------------------------
__global__ __launch_bounds__(NT, 2)
void gemm_kernel(const float* __restrict__ bias, float* __restrict__ out) {
    extern __shared__ char smem[];
    const uint32_t sb = smem_u32(smem);
    const int tid = threadIdx.x;
    const int lane = tid & 31;
    const int wid = tid >> 5;
    const int warp_m = wid & 1;        // 2 warps along M
    const int warp_n = wid >> 1;       // 4 warps along N
    const int m_base = warp_m * 64;
    const int n_base = warp_n * 32;
    const int m0 = blockIdx.y * BM;
    const int n0 = blockIdx.x * BN;

    // cp.async slots as 32-bit byte offsets from scratch bases
    uint32_t ga_off[4], gb_off[4];
    uint32_t sa[4], sbo[4];
#pragma unroll
    for (int i = 0; i < 4; i++) {
        uint32_t idx = tid + i * NT;
        uint32_t r = idx >> 3, c = idx & 7;
        ga_off[i] = ((uint32_t)(m0 + r) * K_DIM + c * 8) * 2;
        sa[i]     = swz(r, c);
        gb_off[i] = ((uint32_t)(n0 + r) * K_DIM + c * 8) * 2;
        sbo[i]    = A_BYTES + swz(r, c);
    }
    const char* gxb = (const char*)g_xh;
    const char* gwb = (const char*)g_wh;

    float acc[4][4][4];
#pragma unroll
    for (int i = 0; i < 4; i++)
#pragma unroll
        for (int j = 0; j < 4; j++)
#pragma unroll
            for (int q = 0; q < 4; q++) acc[i][j][q] = 0.0f;

    // ldmatrix per-thread row components
    const uint32_t a_row = m_base + (lane & 15);       // + i*16
    const uint32_t a_kh  = (lane >> 4) & 1;
    const uint32_t b_row = n_base + (((lane >> 4) & 1) << 3) + (lane & 7); // + jj*16
    const uint32_t b_kh  = (lane >> 3) & 1;

    // ---- prologue: stages 0..1 ----
#pragma unroll
    for (int s = 0; s < STAGES - 1; s++) {
        uint32_t soff = sb + s * STAGE_BYTES;
        uint32_t koff = (uint32_t)s * BK * 2;   // 128 B per kt
#pragma unroll
        for (int i = 0; i < 4; i++) {
            CP_ASYNC16(soff + sa[i], gxb + ga_off[i] + koff);
            CP_ASYNC16(soff + sbo[i], gwb + gb_off[i] + koff);
        }
        CP_COMMIT();
    }

    int stage = 0;          // stage holding kt
#pragma unroll 2
    for (int kt = 0; kt < KT_COUNT; kt++) {
        CP_WAIT1();
        __syncthreads();

        uint32_t As = sb + stage * STAGE_BYTES;
        uint32_t Bs = As + A_BYTES;

        // ---- ks = 0: fragments + MMAs first so tensor work starts now ----
#pragma unroll
        for (int ks = 0; ks < 1; ks++) {
            uint32_t afr[4][4];
#pragma unroll
            for (int i = 0; i < 4; i++) {
                uint32_t addr = As + swz(a_row + i * 16, ks * 2 + a_kh);
                LDM_X4(afr[i][0], afr[i][1], afr[i][2], afr[i][3], addr);
            }
            uint32_t bfr[4][2];
#pragma unroll
            for (int jj = 0; jj < 2; jj++) {
                uint32_t addr = Bs + swz(b_row + jj * 16, ks * 2 + b_kh);
                uint32_t r0, r1, r2, r3;
                LDM_X4(r0, r1, r2, r3, addr);
                bfr[jj * 2][0] = r0;  bfr[jj * 2][1] = r1;
                bfr[jj * 2 + 1][0] = r2; bfr[jj * 2 + 1][1] = r3;
            }
#pragma unroll
            for (int i = 0; i < 4; i++)
#pragma unroll
                for (int j = 0; j < 4; j++)
                    MMA16816(acc[i][j], afr[i], bfr[j]);
        }

        // ---- prefetch kt+2 into the stage freed at kt-1 (after ks0) ----
        {
            int pf = kt + STAGES - 1;
            if (pf < KT_COUNT) {
                int sp = stage + 2;
                if (sp >= STAGES) sp -= STAGES;
                uint32_t soff = sb + sp * STAGE_BYTES;
                uint32_t koff = (uint32_t)pf * BK * 2;
#pragma unroll
                for (int i = 0; i < 4; i++) {
                    CP_ASYNC16(soff + sa[i], gxb + ga_off[i] + koff);
                    CP_ASYNC16(soff + sbo[i], gwb + gb_off[i] + koff);
                }
            }
            CP_COMMIT();   // empty group when done keeps wait invariant
        }
        stage++; if (stage >= STAGES) stage = 0;

        // ---- ks = 1..3 ----
#pragma unroll
        for (int ks = 1; ks < 4; ks++) {
            uint32_t afr[4][4];
#pragma unroll
            for (int i = 0; i < 4; i++) {
                uint32_t addr = As + swz(a_row + i * 16, ks * 2 + a_kh);
                LDM_X4(afr[i][0], afr[i][1], afr[i][2], afr[i][3], addr);
            }
            uint32_t bfr[4][2];
#pragma unroll
            for (int jj = 0; jj < 2; jj++) {
                uint32_t addr = Bs + swz(b_row + jj * 16, ks * 2 + b_kh);
                uint32_t r0, r1, r2, r3;
                LDM_X4(r0, r1, r2, r3, addr);
                bfr[jj * 2][0] = r0;  bfr[jj * 2][1] = r1;
                bfr[jj * 2 + 1][0] = r2; bfr[jj * 2 + 1][1] = r3;
            }
#pragma unroll
            for (int i = 0; i < 4; i++)
#pragma unroll
                for (int j = 0; j < 4; j++)
                    MMA16816(acc[i][j], afr[i], bfr[j]);
        }
    }

    // ---- epilogue: bias + streaming stores ----
    const int tq = lane >> 2;          // row within 16
    const int tr = lane & 3;           // col pair
#pragma unroll
    for (int i = 0; i < 4; i++) {
        size_t mrow0 = (size_t)m0 + m_base + i * 16 + tq;
#pragma unroll
        for (int j = 0; j < 4; j++) {
            int ncol = n0 + n_base + j * 8 + tr * 2;
            float2 bv = __ldg(reinterpret_cast<const float2*>(bias + ncol));
            float2 v0 = {acc[i][j][0] + bv.x, acc[i][j][1] + bv.y};
            float2 v1 = {acc[i][j][2] + bv.x, acc[i][j][3] + bv.y};
            __stcs(reinterpret_cast<float2*>(out + mrow0 * N_DIM + ncol), v0);
            __stcs(reinterpret_cast<float2*>(out + (mrow0 + 8) * N_DIM + ncol), v1);
        }
    }
}

// ---------------------------------------------------------------------------
extern "C" void kernel_launch(void* const* d_in, const int* in_sizes, int n_in,
                              void* d_out, int out_size) {
    const float* x      = (const float*)d_in[0];
    const int*   packed = (const int*)d_in[1];
    const float* mn     = (const float*)d_in[2];
    const float* scale  = (const float*)d_in[3];
    const float* bias   = (const float*)d_in[4];
    float* out = (float*)d_out;

    const int M = in_sizes[0] / K_DIM;                 // 8192

    cudaFuncSetAttribute(gemm_kernel,
                         cudaFuncAttributeMaxDynamicSharedMemorySize, SMEM_TOTAL);

    const int xblocks = (int)(((size_t)M * K_DIM / 8) / 512);            // 8192
    const int wblocks = (N_DIM * NUM_GROUPS * 8) / 512;                  // 4096
    prep_kernel<<<xblocks + wblocks, 512>>>(x, packed, mn, scale, xblocks);

    dim3 grid(N_DIM / BN, M / BM);                     // (32, 64)
    gemm_kernel<<<grid, NT, SMEM_TOTAL>>>(bias, out);
}